// round 3
// baseline (speedup 1.0000x reference)
#include <cuda_runtime.h>
#include <cstdint>
#include <cstddef>

#define Bz 64
#define Sz 2048
#define Hz 256
#define NCTA 96

// ---------------- scratch (static device arrays: no runtime allocation) -----
__device__ float g_A0[(size_t)Bz * Sz * Hz];   // x@w_h0 + b_h0, [B,S,H]
__device__ float g_H1[(size_t)Bz * Sz * Hz];   // h1 states,     [B,S,H]
__device__ float g_h0r[2][Bz * Hz];            // h0 state ring
__device__ float g_h1r[2][Bz * Hz];            // h1 state ring
__device__ float g_a1r[2][Bz * Hz];            // staged h0n@w_h1 + b_h1
__device__ unsigned g_cnt;
__device__ volatile unsigned g_gen;

// ---------------- init: reset rings + barrier each launch (determinism) -----
__global__ void init_k() {
    int i = blockIdx.x * blockDim.x + threadIdx.x;
    if (i == 0) { g_cnt = 0; g_gen = 0; }
    if (i < 2 * Bz * Hz) {
        ((float*)g_h0r)[i] = 0.f;
        ((float*)g_h1r)[i] = 0.f;
        ((float*)g_a1r)[i] = 0.f;
    }
}

// ---------------- C[M,256] = A[M,256] @ W[256,256] + bias -------------------
__global__ __launch_bounds__(256) void gemm256(const float* __restrict__ A,
                                               const float* __restrict__ W,
                                               const float* __restrict__ bias,
                                               float* __restrict__ C) {
    __shared__ float As[64][68];   // [m][k], pad 68 => conflict-free column reads
    __shared__ float Ws[64][64];   // [k][n]
    const int tid = threadIdx.x;
    const int tm = tid >> 4, tn = tid & 15;
    const int m0 = blockIdx.x * 64, n0 = blockIdx.y * 64;

    float acc[4][4] = {};
    const float4 bv = *(const float4*)&bias[n0 + tn * 4];

    for (int k0 = 0; k0 < 256; k0 += 64) {
#pragma unroll
        for (int f = 0; f < 4; ++f) {
            int v  = tid + f * 256;        // 0..1023
            int r0 = v >> 4;               // 0..63
            int c4 = (v & 15) << 2;        // 0..60
            *(float4*)&As[r0][c4] = *(const float4*)&A[(size_t)(m0 + r0) * 256 + k0 + c4];
            *(float4*)&Ws[r0][c4] = *(const float4*)&W[(size_t)(k0 + r0) * 256 + n0 + c4];
        }
        __syncthreads();
#pragma unroll 16
        for (int kk = 0; kk < 64; ++kk) {
            float4 w = *(const float4*)&Ws[kk][tn * 4];
            float a0 = As[tm * 4 + 0][kk];
            float a1 = As[tm * 4 + 1][kk];
            float a2 = As[tm * 4 + 2][kk];
            float a3 = As[tm * 4 + 3][kk];
            acc[0][0] += a0 * w.x; acc[0][1] += a0 * w.y; acc[0][2] += a0 * w.z; acc[0][3] += a0 * w.w;
            acc[1][0] += a1 * w.x; acc[1][1] += a1 * w.y; acc[1][2] += a1 * w.z; acc[1][3] += a1 * w.w;
            acc[2][0] += a2 * w.x; acc[2][1] += a2 * w.y; acc[2][2] += a2 * w.z; acc[2][3] += a2 * w.w;
            acc[3][0] += a3 * w.x; acc[3][1] += a3 * w.y; acc[3][2] += a3 * w.z; acc[3][3] += a3 * w.w;
        }
        __syncthreads();
    }
#pragma unroll
    for (int i = 0; i < 4; ++i) {
        float4 o = make_float4(acc[i][0] + bv.x, acc[i][1] + bv.y,
                               acc[i][2] + bv.z, acc[i][3] + bv.w);
        *(float4*)&C[(size_t)(m0 + tm * 4 + i) * 256 + n0 + tn * 4] = o;
    }
}

// ---------------- persistent pipelined recurrence ---------------------------
// 96 CTAs = 3 matrices (u_h0 / w_h1 / u_h1) x 8 batch-groups(8b) x 4 col-groups(64j).
// Interval t computes: layer0 step t; A1(t-1)=h0n(t-1)@w_h1+b; layer1 step t-2.
// => inputs of every group were published before the previous barrier: 1 barrier/step.
__global__ void __launch_bounds__(128, 1)
rnn_k(const float* __restrict__ u_h0, const float* __restrict__ w_h1,
      const float* __restrict__ u_h1, const float* __restrict__ b_h1,
      float* __restrict__ hf /* d_out + B*S*O : h_final [B,2,H] */) {
    extern __shared__ float smem[];
    float* ws = smem;              // 256 x 64 weight slice (persistent)
    float* hs = smem + 256 * 64;   // transposed state hs[k][bi], row pad 10 (2560 f)

    const int tid = threadIdx.x;
    const int c = blockIdx.x;
    const int m = c >> 5;                 // 0:u_h0  1:w_h1  2:u_h1  (== pipeline lag)
    const int r = c & 31;
    const int b0 = (r >> 2) * 8;
    const int j0 = (r & 3) * 64;

    // load persistent weight slice into smem
    const float* Wsrc = (m == 0) ? u_h0 : (m == 1) ? w_h1 : u_h1;
    for (int idx = tid; idx < 256 * 64; idx += 128)
        ws[idx] = Wsrc[(size_t)(idx >> 6) * 256 + j0 + (idx & 63)];

    const int ks = tid >> 6;          // k-split half (0/1)
    const int bt = (tid >> 4) & 3;    // batch tile (2 b each)
    const int jt = tid & 15;          // col tile (4 j each)
    const int ba = b0 + bt * 2;
    const int jb = j0 + jt * 4;

    float4 bias4 = make_float4(0.f, 0.f, 0.f, 0.f);
    if (m == 1) bias4 = *(const float4*)&b_h1[jb];

    unsigned gen = 0;
    __syncthreads();

    for (int t = 0; t < Sz + 2; ++t) {
        const int tc = t - m;
        if (tc >= 0 && tc < Sz) {
            const float* src = (m <= 1) ? g_h0r[(t - 1) & 1] : g_h1r[(t - 3) & 1];

            // prefetch epilogue operands early (hidden behind the k-loop)
            float4 e0, e1;
            e0 = e1 = make_float4(0.f, 0.f, 0.f, 0.f);
            if (ks == 0) {
                if (m == 0) {
                    e0 = *(const float4*)&g_A0[((size_t)ba * Sz + tc) * 256 + jb];
                    e1 = *(const float4*)&g_A0[((size_t)(ba + 1) * Sz + tc) * 256 + jb];
                } else if (m == 2) {
                    const float* a1 = g_a1r[tc & 1];
                    e0 = *(const float4*)&a1[ba * 256 + jb];
                    e1 = *(const float4*)&a1[(ba + 1) * 256 + jb];
                }
            }

            // load this group's 8 state rows, transposed: hs[k*10 + bi]
            for (int idx = tid; idx < 2048; idx += 128) {
                int bi = idx >> 8, k = idx & 255;
                hs[k * 10 + bi] = src[(b0 + bi) * 256 + k];
            }
            __syncthreads();

            float4 acc0 = make_float4(0.f, 0.f, 0.f, 0.f);
            float4 acc1 = make_float4(0.f, 0.f, 0.f, 0.f);
            {
                const float4* wp = (const float4*)ws + (ks ? 128 * 16 : 0) + jt;
                const float2* hp = (const float2*)hs + (ks ? 128 * 5 : 0) + bt;
#pragma unroll 4
                for (int k = 0; k < 128; ++k) {
                    float4 w = wp[k * 16];
                    float2 h = hp[k * 5];
                    acc0.x += h.x * w.x; acc0.y += h.x * w.y;
                    acc0.z += h.x * w.z; acc0.w += h.x * w.w;
                    acc1.x += h.y * w.x; acc1.y += h.y * w.y;
                    acc1.z += h.y * w.z; acc1.w += h.y * w.w;
                }
            }
            __syncthreads();

            // k-split reduction through smem (reuse hs region)
            float4* ps = (float4*)hs;
            const int tile = bt * 16 + jt;
            if (ks == 1) { ps[tile * 2] = acc0; ps[tile * 2 + 1] = acc1; }
            __syncthreads();

            if (ks == 0) {
                float4 p0 = ps[tile * 2], p1 = ps[tile * 2 + 1];
                acc0.x += p0.x; acc0.y += p0.y; acc0.z += p0.z; acc0.w += p0.w;
                acc1.x += p1.x; acc1.y += p1.y; acc1.z += p1.z; acc1.w += p1.w;
                const int slot = tc & 1;
                if (m == 0) {
                    float4 v0, v1;
                    v0.x = tanhf(acc0.x + e0.x); v0.y = tanhf(acc0.y + e0.y);
                    v0.z = tanhf(acc0.z + e0.z); v0.w = tanhf(acc0.w + e0.w);
                    v1.x = tanhf(acc1.x + e1.x); v1.y = tanhf(acc1.y + e1.y);
                    v1.z = tanhf(acc1.z + e1.z); v1.w = tanhf(acc1.w + e1.w);
                    *(float4*)&g_h0r[slot][ba * 256 + jb] = v0;
                    *(float4*)&g_h0r[slot][(ba + 1) * 256 + jb] = v1;
                    if (tc == Sz - 1) {
                        *(float4*)&hf[(ba * 2 + 0) * 256 + jb] = v0;
                        *(float4*)&hf[((ba + 1) * 2 + 0) * 256 + jb] = v1;
                    }
                } else if (m == 1) {
                    float4 v0 = make_float4(acc0.x + bias4.x, acc0.y + bias4.y,
                                            acc0.z + bias4.z, acc0.w + bias4.w);
                    float4 v1 = make_float4(acc1.x + bias4.x, acc1.y + bias4.y,
                                            acc1.z + bias4.z, acc1.w + bias4.w);
                    *(float4*)&g_a1r[slot][ba * 256 + jb] = v0;
                    *(float4*)&g_a1r[slot][(ba + 1) * 256 + jb] = v1;
                } else {
                    float4 v0, v1;
                    v0.x = tanhf(acc0.x + e0.x); v0.y = tanhf(acc0.y + e0.y);
                    v0.z = tanhf(acc0.z + e0.z); v0.w = tanhf(acc0.w + e0.w);
                    v1.x = tanhf(acc1.x + e1.x); v1.y = tanhf(acc1.y + e1.y);
                    v1.z = tanhf(acc1.z + e1.z); v1.w = tanhf(acc1.w + e1.w);
                    *(float4*)&g_h1r[slot][ba * 256 + jb] = v0;
                    *(float4*)&g_h1r[slot][(ba + 1) * 256 + jb] = v1;
                    *(float4*)&g_H1[((size_t)ba * Sz + tc) * 256 + jb] = v0;
                    *(float4*)&g_H1[((size_t)(ba + 1) * Sz + tc) * 256 + jb] = v1;
                    if (tc == Sz - 1) {
                        *(float4*)&hf[(ba * 2 + 1) * 256 + jb] = v0;
                        *(float4*)&hf[((ba + 1) * 2 + 1) * 256 + jb] = v1;
                    }
                }
            }
        }

        // ---- grid barrier (sense via generation counter) ----
        __syncthreads();
        if (tid == 0) {
            __threadfence();
            unsigned old = atomicAdd(&g_cnt, 1u);
            if (old == NCTA - 1) {
                atomicExch(&g_cnt, 0u);
                __threadfence();
                g_gen = gen + 1;
            } else {
                while (g_gen == gen) { }
            }
            __threadfence();
        }
        gen++;
        __syncthreads();
    }
}

// ---------------- launch ----------------------------------------------------
extern "C" void kernel_launch(void* const* d_in, const int* in_sizes, int n_in,
                              void* d_out, int out_size) {
    const float* x    = (const float*)d_in[0];
    const float* w_h0 = (const float*)d_in[1];
    const float* u_h0 = (const float*)d_in[2];
    const float* b_h0 = (const float*)d_in[3];
    const float* w_h1 = (const float*)d_in[4];
    const float* u_h1 = (const float*)d_in[5];
    const float* b_h1 = (const float*)d_in[6];
    const float* w_q  = (const float*)d_in[7];
    const float* b_q  = (const float*)d_in[8];

    float* out = (float*)d_out;                       // [B,S,O]
    float* hf  = out + (size_t)Bz * Sz * Hz;          // [B,2,H]

    float *pA0 = nullptr, *pH1 = nullptr;
    cudaGetSymbolAddress((void**)&pA0, g_A0);
    cudaGetSymbolAddress((void**)&pH1, g_H1);

    const int smem_bytes = (256 * 64 + 256 * 10) * 4; // 75776 B
    cudaFuncSetAttribute(rnn_k, cudaFuncAttributeMaxDynamicSharedMemorySize, smem_bytes);

    init_k<<<128, 256>>>();
    gemm256<<<dim3((Bz * Sz) / 64, 4), 256>>>(x, w_h0, b_h0, pA0);
    rnn_k<<<NCTA, 128, smem_bytes>>>(u_h0, w_h1, u_h1, b_h1, hf);
    gemm256<<<dim3((Bz * Sz) / 64, 4), 256>>>(pH1, w_q, b_q, out);
}

// round 4
// speedup vs baseline: 1.0839x; 1.0839x over previous
#include <cuda_runtime.h>
#include <cstdint>
#include <cstddef>

#define Bz 64
#define Sz 2048
#define Hz 256

typedef unsigned long long ull;

// ---------------- scratch (static device arrays: no runtime allocation) -----
__device__ float g_A0[(size_t)Bz * Sz * Hz];   // x@w_h0 + b_h0, [B,S,H]
__device__ float g_H1[(size_t)Bz * Sz * Hz];   // h1 states,     [B,S,H]
__device__ float g_h0r[2][Bz * Hz];            // h0 state ring
__device__ float g_h1r[2][Bz * Hz];            // h1 state ring

// packed fp32x2 FMA (sm_100+): d = a*b + c elementwise on 2 packed floats
__device__ __forceinline__ ull ffma2(ull a, ull b, ull c) {
    ull d;
    asm("fma.rn.f32x2 %0, %1, %2, %3;" : "=l"(d) : "l"(a), "l"(b), "l"(c));
    return d;
}

// ---------------- init: zero state rings each launch (determinism) ----------
__global__ void init_k() {
    int i = blockIdx.x * blockDim.x + threadIdx.x;
    if (i < 2 * Bz * Hz) {
        ((float*)g_h0r)[i] = 0.f;
        ((float*)g_h1r)[i] = 0.f;
    }
}

// ---------------- C[M,256] = A[M,256] @ W[256,256] + bias -------------------
__global__ __launch_bounds__(256) void gemm256(const float* __restrict__ A,
                                               const float* __restrict__ W,
                                               const float* __restrict__ bias,
                                               float* __restrict__ C) {
    __shared__ float As[64][68];   // [m][k], pad 68 => conflict-free column reads
    __shared__ float Ws[64][64];   // [k][n]
    const int tid = threadIdx.x;
    const int tm = tid >> 4, tn = tid & 15;
    const int m0 = blockIdx.x * 64, n0 = blockIdx.y * 64;

    float acc[4][4] = {};
    const float4 bv = *(const float4*)&bias[n0 + tn * 4];

    for (int k0 = 0; k0 < 256; k0 += 64) {
#pragma unroll
        for (int f = 0; f < 4; ++f) {
            int v  = tid + f * 256;
            int r0 = v >> 4;
            int c4 = (v & 15) << 2;
            *(float4*)&As[r0][c4] = *(const float4*)&A[(size_t)(m0 + r0) * 256 + k0 + c4];
            *(float4*)&Ws[r0][c4] = *(const float4*)&W[(size_t)(k0 + r0) * 256 + n0 + c4];
        }
        __syncthreads();
#pragma unroll 16
        for (int kk = 0; kk < 64; ++kk) {
            float4 w = *(const float4*)&Ws[kk][tn * 4];
            float a0 = As[tm * 4 + 0][kk];
            float a1 = As[tm * 4 + 1][kk];
            float a2 = As[tm * 4 + 2][kk];
            float a3 = As[tm * 4 + 3][kk];
            acc[0][0] += a0 * w.x; acc[0][1] += a0 * w.y; acc[0][2] += a0 * w.z; acc[0][3] += a0 * w.w;
            acc[1][0] += a1 * w.x; acc[1][1] += a1 * w.y; acc[1][2] += a1 * w.z; acc[1][3] += a1 * w.w;
            acc[2][0] += a2 * w.x; acc[2][1] += a2 * w.y; acc[2][2] += a2 * w.z; acc[2][3] += a2 * w.w;
            acc[3][0] += a3 * w.x; acc[3][1] += a3 * w.y; acc[3][2] += a3 * w.z; acc[3][3] += a3 * w.w;
        }
        __syncthreads();
    }
#pragma unroll
    for (int i = 0; i < 4; ++i) {
        float4 o = make_float4(acc[i][0] + bv.x, acc[i][1] + bv.y,
                               acc[i][2] + bv.z, acc[i][3] + bv.w);
        *(float4*)&C[(size_t)(m0 + tm * 4 + i) * 256 + n0 + tn * 4] = o;
    }
}

// ---------------- persistent clustered recurrence ---------------------------
// 16 clusters x 8 CTAs. Cluster g owns batch rows [4g, 4g+4); CTA rank r owns
// columns [32r, 32r+32) of all three matrices (u_h0, w_h1, u_h1).
// Interval t (software pipeline, ONE cluster barrier per step):
//   G0: h0n[t]   = tanh(A0[t] + h0n[t-1] @ u_h0)          (publish to L2 ring)
//   G1: a1[t-1]  = h0n[t-1] @ w_h1 + b_h1                 (kept in CTA smem)
//   G2: h1n[t-2] = tanh(a1[t-2] + h1n[t-3] @ u_h1)        (publish + stream to g_H1)
// Clusters never communicate with each other (batch-independent).

#define WS_PER_M 8192           // 256 k * 32 cols
#define HS_STRIDE 12            // dup-state row stride (floats): 8 used + 4 pad
#define PS_STRIDE 388           // partial row stride: 384 + 4 pad

__global__ void __cluster_dims__(8, 1, 1) __launch_bounds__(128, 1)
rnn_k(const float* __restrict__ u_h0, const float* __restrict__ w_h1,
      const float* __restrict__ u_h1, const float* __restrict__ b_h1,
      float* __restrict__ hf /* d_out + B*S*O : h_final [B,2,H] */) {
    extern __shared__ float sm[];
    float* ws  = sm;                        // 3 * 8192 weight slices
    float* hs0 = sm + 3 * WS_PER_M;         // 256*12 dup h0n state
    float* hs1 = hs0 + 256 * HS_STRIDE;     // 256*12 dup h1n state
    float* ps  = hs1 + 256 * HS_STRIDE;     // 16*388 k-split partials
    float* a1s = ps + 16 * PS_STRIDE;       // 2*128 local a1 ring

    const int tid  = threadIdx.x;
    const int w    = tid >> 5;              // warp = k-quarter
    const int lane = tid & 31;
    const int ks   = lane >> 3;             // k sixteenth within quarter
    const int jt   = lane & 7;              // 4-col group
    const int bg   = (blockIdx.x >> 3) * 4; // first batch row of cluster
    const int j0   = (blockIdx.x & 7) * 32; // first col of this CTA

    // persistent weight slices: ws[m][k*32 + c] = W_m[k][j0+c]
    for (int idx = tid; idx < 3 * WS_PER_M; idx += 128) {
        int m = idx >> 13, rem = idx & (WS_PER_M - 1);
        int k = rem >> 5, c = rem & 31;
        const float* W = (m == 0) ? u_h0 : (m == 1) ? w_h1 : u_h1;
        ws[idx] = W[(size_t)k * 256 + j0 + c];
    }

    const int er = tid >> 5;                // epilogue row (0..3)
    const int ec = tid & 31;                // epilogue col (0..31)
    const float bias = b_h1[j0 + ec];

    const int kbase = w * 64 + ks * 16;
    const float* wp0 = ws + (size_t)kbase * 32 + jt * 4;

    __syncthreads();

    for (int t = 0; t < Sz + 2; ++t) {
        // A0 prefetch for this step's layer-0 epilogue (DRAM, hidden by loop)
        float a0v = 0.f;
        if (t < Sz)
            a0v = __ldcg(&g_A0[((size_t)(bg + er) * Sz + t) * 256 + j0 + ec]);

        // stage states from L2 rings into duplicated smem: hs[k*12 + 2b] = (h,h)
        {
            const float* sh0 = g_h0r[(t + 1) & 1] + (bg + er) * 256; // h0n[t-1]
            const float* sh1 = g_h1r[(t + 1) & 1] + (bg + er) * 256; // h1n[t-3]
            float v0[8], v1[8];
#pragma unroll
            for (int i = 0; i < 8; ++i) v0[i] = __ldcg(&sh0[ec + i * 32]);
#pragma unroll
            for (int i = 0; i < 8; ++i) v1[i] = __ldcg(&sh1[ec + i * 32]);
#pragma unroll
            for (int i = 0; i < 8; ++i) {
                int k = ec + i * 32;
                *(float2*)&hs0[k * HS_STRIDE + 2 * er] = make_float2(v0[i], v0[i]);
                *(float2*)&hs1[k * HS_STRIDE + 2 * er] = make_float2(v1[i], v1[i]);
            }
        }
        __syncthreads();

        // three GEMM partials, 16-way k-split, packed f32x2 math
        ull acc[3][4][2];
#pragma unroll
        for (int m = 0; m < 3; ++m)
#pragma unroll
            for (int r = 0; r < 4; ++r) { acc[m][r][0] = 0ull; acc[m][r][1] = 0ull; }

#pragma unroll
        for (int m = 0; m < 3; ++m) {
            const float* wp = wp0 + m * WS_PER_M;
            const float* hp = ((m == 2) ? hs1 : hs0) + (size_t)kbase * HS_STRIDE;
#pragma unroll 4
            for (int kk = 0; kk < 16; ++kk) {
                ulonglong2 wv = *(const ulonglong2*)(wp + kk * 32);
                ulonglong2 ha = *(const ulonglong2*)(hp + kk * HS_STRIDE);     // rows 0,1
                ulonglong2 hb = *(const ulonglong2*)(hp + kk * HS_STRIDE + 4); // rows 2,3
                acc[m][0][0] = ffma2(ha.x, wv.x, acc[m][0][0]);
                acc[m][0][1] = ffma2(ha.x, wv.y, acc[m][0][1]);
                acc[m][1][0] = ffma2(ha.y, wv.x, acc[m][1][0]);
                acc[m][1][1] = ffma2(ha.y, wv.y, acc[m][1][1]);
                acc[m][2][0] = ffma2(hb.x, wv.x, acc[m][2][0]);
                acc[m][2][1] = ffma2(hb.x, wv.y, acc[m][2][1]);
                acc[m][3][0] = ffma2(hb.y, wv.x, acc[m][3][0]);
                acc[m][3][1] = ffma2(hb.y, wv.y, acc[m][3][1]);
            }
        }

        // store k-split partials
        {
            float* pb = ps + (size_t)(w * 4 + ks) * PS_STRIDE + jt * 4;
#pragma unroll
            for (int m = 0; m < 3; ++m)
#pragma unroll
                for (int r = 0; r < 4; ++r)
                    *(ulonglong2*)&pb[(m * 4 + r) * 32] =
                        make_ulonglong2(acc[m][r][0], acc[m][r][1]);
        }
        __syncthreads();

        // reduce 16 partials: thread tid owns output (row er, col ec) of each matrix
        float s0 = 0.f, s1 = 0.f, s2 = 0.f;
#pragma unroll
        for (int p = 0; p < 16; ++p) {
            s0 += ps[p * PS_STRIDE + tid];
            s1 += ps[p * PS_STRIDE + 128 + tid];
            s2 += ps[p * PS_STRIDE + 256 + tid];
        }

        const int gofs = (bg + er) * 256 + j0 + ec;
        if (t < Sz) {                                   // G0: h0n[t]
            float v = tanhf(s0 + a0v);
            g_h0r[t & 1][gofs] = v;
            if (t == Sz - 1) hf[((bg + er) * 2 + 0) * 256 + j0 + ec] = v;
        }
        if (t >= 1 && t <= Sz)                          // G1: a1[t-1] (local)
            a1s[(t & 1) * 128 + tid] = s1 + bias;
        if (t >= 2) {                                   // G2: h1n[t-2]
            float v = tanhf(s2 + a1s[((t - 1) & 1) * 128 + tid]);
            g_h1r[t & 1][gofs] = v;                     // slot (t-2)&1 == t&1
            g_H1[((size_t)(bg + er) * Sz + (t - 2)) * 256 + j0 + ec] = v;
            if (t == Sz + 1) hf[((bg + er) * 2 + 1) * 256 + j0 + ec] = v;
        }

        // one cluster barrier per step (release/acquire orders the ring STG/LDG)
        asm volatile("barrier.cluster.arrive.aligned;" ::: "memory");
        asm volatile("barrier.cluster.wait.aligned;" ::: "memory");
    }
}

// ---------------- launch ----------------------------------------------------
extern "C" void kernel_launch(void* const* d_in, const int* in_sizes, int n_in,
                              void* d_out, int out_size) {
    const float* x    = (const float*)d_in[0];
    const float* w_h0 = (const float*)d_in[1];
    const float* u_h0 = (const float*)d_in[2];
    const float* b_h0 = (const float*)d_in[3];
    const float* w_h1 = (const float*)d_in[4];
    const float* u_h1 = (const float*)d_in[5];
    const float* b_h1 = (const float*)d_in[6];
    const float* w_q  = (const float*)d_in[7];
    const float* b_q  = (const float*)d_in[8];

    float* out = (float*)d_out;                       // [B,S,O]
    float* hf  = out + (size_t)Bz * Sz * Hz;          // [B,2,H]

    float *pA0 = nullptr, *pH1 = nullptr;
    cudaGetSymbolAddress((void**)&pA0, g_A0);
    cudaGetSymbolAddress((void**)&pH1, g_H1);

    const int smem_bytes = (3 * WS_PER_M + 2 * 256 * HS_STRIDE +
                            16 * PS_STRIDE + 2 * 128) * 4;   // 148736 B
    cudaFuncSetAttribute(rnn_k, cudaFuncAttributeMaxDynamicSharedMemorySize, smem_bytes);

    init_k<<<128, 256>>>();
    gemm256<<<dim3((Bz * Sz) / 64, 4), 256>>>(x, w_h0, b_h0, pA0);
    rnn_k<<<128, 128, smem_bytes>>>(u_h0, w_h1, u_h1, b_h1, hf);
    gemm256<<<dim3((Bz * Sz) / 64, 4), 256>>>(pH1, w_q, b_q, out);
}

// round 5
// speedup vs baseline: 2.6842x; 2.4765x over previous
#include <cuda_runtime.h>
#include <cstdint>
#include <cstddef>

#define Bz 64
#define Sz 2048
#define Hz 256

typedef unsigned long long ull;

// ---------------- scratch (static device arrays: no runtime allocation) -----
__device__ float g_A0[(size_t)Bz * Sz * Hz];   // x@w_h0 + b_h0, [B,S,H]
__device__ float g_H1[(size_t)Bz * Sz * Hz];   // h1 states,     [B,S,H]
__device__ float g_h0r[2][Bz * Hz];            // h0 state ring  [slot][b*256+k]
__device__ float g_h1r[2][Bz * Hz];            // h1 state ring

// packed fp32x2 FMA (sm_100+)
__device__ __forceinline__ ull ffma2(ull a, ull b, ull c) {
    ull d;
    asm("fma.rn.f32x2 %0, %1, %2, %3;" : "=l"(d) : "l"(a), "l"(b), "l"(c));
    return d;
}
__device__ __forceinline__ ull dupf(float x) {
    ull r;
    asm("mov.b64 %0, {%1, %1};" : "=l"(r) : "f"(x));
    return r;
}
__device__ __forceinline__ float2 asf2(ull u) {
    float2 f;
    asm("mov.b64 {%0, %1}, %2;" : "=f"(f.x), "=f"(f.y) : "l"(u));
    return f;
}

// ---------------- init: zero state rings each launch (determinism) ----------
__global__ void init_k() {
    int i = blockIdx.x * blockDim.x + threadIdx.x;
    if (i < 2 * Bz * Hz) {
        ((float*)g_h0r)[i] = 0.f;
        ((float*)g_h1r)[i] = 0.f;
    }
}

// ---------------- C[M,256] = A[M,256] @ W[256,256] + bias (f32x2 math) ------
__global__ __launch_bounds__(256) void gemm256(const float* __restrict__ A,
                                               const float* __restrict__ W,
                                               const float* __restrict__ bias,
                                               float* __restrict__ C) {
    __shared__ float As[64][68];
    __shared__ float Ws[64][64];
    const int tid = threadIdx.x;
    const int tm = tid >> 4, tn = tid & 15;
    const int m0 = blockIdx.x * 64, n0 = blockIdx.y * 64;

    ull acc[4][2];
#pragma unroll
    for (int i = 0; i < 4; ++i) { acc[i][0] = 0ull; acc[i][1] = 0ull; }
    const float4 bv = *(const float4*)&bias[n0 + tn * 4];

    for (int k0 = 0; k0 < 256; k0 += 64) {
#pragma unroll
        for (int f = 0; f < 4; ++f) {
            int v  = tid + f * 256;
            int r0 = v >> 4;
            int c4 = (v & 15) << 2;
            *(float4*)&As[r0][c4] = *(const float4*)&A[(size_t)(m0 + r0) * 256 + k0 + c4];
            *(float4*)&Ws[r0][c4] = *(const float4*)&W[(size_t)(k0 + r0) * 256 + n0 + c4];
        }
        __syncthreads();
#pragma unroll 8
        for (int kk = 0; kk < 64; ++kk) {
            ulonglong2 wv = *(const ulonglong2*)&Ws[kk][tn * 4];
#pragma unroll
            for (int i = 0; i < 4; ++i) {
                ull d = dupf(As[tm * 4 + i][kk]);
                acc[i][0] = ffma2(d, wv.x, acc[i][0]);
                acc[i][1] = ffma2(d, wv.y, acc[i][1]);
            }
        }
        __syncthreads();
    }
#pragma unroll
    for (int i = 0; i < 4; ++i) {
        float2 lo = asf2(acc[i][0]), hi = asf2(acc[i][1]);
        float4 o = make_float4(lo.x + bv.x, lo.y + bv.y, hi.x + bv.z, hi.y + bv.w);
        *(float4*)&C[(size_t)(m0 + tm * 4 + i) * 256 + n0 + tn * 4] = o;
    }
}

// ---------------- persistent clustered recurrence ---------------------------
// 32 clusters x 4 CTAs x 512 threads. Cluster g owns batch rows {2g, 2g+1};
// CTA rank r owns columns [64r, 64r+64) of u_h0 / w_h1 / u_h1.
// ALL WEIGHTS LIVE IN REGISTERS: thread (ks=warp, jg=lane) holds, for each of
// the 3 matrices, k-rows [16ks,16ks+16) x j-cols {j0+2jg, j0+2jg+1} packed as
// 48 ull. Per step only the 2-row state vectors move through smem (broadcast).
// Software pipeline (one cluster barrier per step):
//   G0: h0n[t]   = tanh(A0[t] + h0n[t-1]@u_h0)   -> L2 ring slot t&1
//   G1: a1[t-1]  = h0n[t-1]@w_h1 + b_h1          -> local smem ring
//   G2: h1n[t-2] = tanh(a1[t-2] + h1n[t-3]@u_h1) -> L2 ring slot t&1, g_H1

#define PS 392   // partial row stride (floats), 384 used

__global__ void __cluster_dims__(4, 1, 1) __launch_bounds__(512, 1)
rnn_k(const float* __restrict__ u_h0, const float* __restrict__ w_h1,
      const float* __restrict__ u_h1, const float* __restrict__ b_h1,
      float* __restrict__ hf) {
    __shared__ float hs0[256 * 4];      // dup state: hs0[k*4+2b] = (h0,h0)
    __shared__ float hs1[256 * 4];
    __shared__ float ps[16 * PS];       // k-split partials
    __shared__ float a1s[2 * 128];      // local a1 ring

    const int tid = threadIdx.x;
    const int ks  = tid >> 5;                 // warp id = k-split (16)
    const int jg  = tid & 31;                 // lane = j-group (2 cols)
    const int bg  = (blockIdx.x >> 2) * 2;    // first batch row of cluster
    const int j0  = (blockIdx.x & 3) * 64;    // first col of this CTA

    // ---- persistent weights in registers: 3 x 16 packed col-pairs ----
    ull wr0[16], wr1[16], wr2[16];
#pragma unroll
    for (int kk = 0; kk < 16; ++kk) {
        size_t o = (size_t)(ks * 16 + kk) * 256 + j0 + jg * 2;
        wr0[kk] = __ldg((const ull*)&u_h0[o]);
        wr1[kk] = __ldg((const ull*)&w_h1[o]);
        wr2[kk] = __ldg((const ull*)&u_h1[o]);
    }

    // epilogue identity: threads [0,384): o = m*128 + b*64 + j
    const int eo = tid;
    const int em = eo >> 7;
    const int er = eo & 127;
    const int eb = er >> 6;
    const int ej = er & 63;
    const float bias = b_h1[j0 + ej];

    // stage identity: thread -> (b = tid>>8, k = tid&255)
    const int sb = tid >> 8, sk = tid & 255;

    for (int t = 0; t < Sz + 2; ++t) {
        // A0 prefetch for G0 epilogue (L2/DRAM, hidden behind the step)
        float a0v = 0.f;
        if (em == 0 && t < Sz && eo < 384)
            a0v = __ldcg(&g_A0[((size_t)(bg + eb) * Sz + t) * 256 + j0 + ej]);

        // ---- stage states from L2 rings into duplicated smem ----
        {
            const int sl = (t + 1) & 1;       // h0n[t-1] / h1n[t-3] parity
            float v0 = __ldcg(&g_h0r[sl][(bg + sb) * 256 + sk]);
            float v1 = __ldcg(&g_h1r[sl][(bg + sb) * 256 + sk]);
            *(ull*)&hs0[sk * 4 + 2 * sb] = dupf(v0);
            *(ull*)&hs1[sk * 4 + 2 * sb] = dupf(v1);
        }
        __syncthreads();

        // ---- main: 3 GEMM partials, weights from regs, states broadcast ----
        ull a00 = 0, a01 = 0, a10 = 0, a11 = 0, a20 = 0, a21 = 0;
        {
            const float* h0p = hs0 + ks * 64;   // 16 k-rows * 4 floats
            const float* h1p = hs1 + ks * 64;
#pragma unroll
            for (int kk = 0; kk < 16; ++kk) {
                ulonglong2 h0 = *(const ulonglong2*)(h0p + kk * 4);
                ulonglong2 h1 = *(const ulonglong2*)(h1p + kk * 4);
                a00 = ffma2(h0.x, wr0[kk], a00);
                a01 = ffma2(h0.y, wr0[kk], a01);
                a10 = ffma2(h0.x, wr1[kk], a10);
                a11 = ffma2(h0.y, wr1[kk], a11);
                a20 = ffma2(h1.x, wr2[kk], a20);
                a21 = ffma2(h1.y, wr2[kk], a21);
            }
        }
        // store k-split partials: ps[ks][m*128 + b*64 + jg*2]
        {
            float* pb = ps + ks * PS + jg * 2;
            *(ull*)&pb[0]        = a00;  *(ull*)&pb[64]       = a01;
            *(ull*)&pb[128]      = a10;  *(ull*)&pb[192]      = a11;
            *(ull*)&pb[256]      = a20;  *(ull*)&pb[320]      = a21;
        }
        __syncthreads();

        // ---- reduce 16 partials + epilogue ----
        if (eo < 384) {
            float s = 0.f;
#pragma unroll
            for (int p = 0; p < 16; ++p) s += ps[p * PS + eo];

            const int gofs = (bg + eb) * 256 + j0 + ej;
            if (em == 0) {
                if (t < Sz) {
                    float v = tanhf(s + a0v);
                    g_h0r[t & 1][gofs] = v;
                    if (t == Sz - 1) hf[((bg + eb) * 2 + 0) * 256 + j0 + ej] = v;
                }
            } else if (em == 1) {
                if (t >= 1 && t <= Sz)
                    a1s[((t - 1) & 1) * 128 + er] = s + bias;   // a1[t-1]
            } else {
                if (t >= 2) {
                    float v = tanhf(s + a1s[(t & 1) * 128 + er]); // + a1[t-2]
                    g_h1r[t & 1][gofs] = v;
                    g_H1[((size_t)(bg + eb) * Sz + (t - 2)) * 256 + j0 + ej] = v;
                    if (t == Sz + 1) hf[((bg + eb) * 2 + 1) * 256 + j0 + ej] = v;
                }
            }
        }

        // ---- one cluster barrier per step (release/acquire orders rings) ----
        asm volatile("barrier.cluster.arrive.aligned;" ::: "memory");
        asm volatile("barrier.cluster.wait.aligned;" ::: "memory");
    }
}

// ---------------- launch ----------------------------------------------------
extern "C" void kernel_launch(void* const* d_in, const int* in_sizes, int n_in,
                              void* d_out, int out_size) {
    const float* x    = (const float*)d_in[0];
    const float* w_h0 = (const float*)d_in[1];
    const float* u_h0 = (const float*)d_in[2];
    const float* b_h0 = (const float*)d_in[3];
    const float* w_h1 = (const float*)d_in[4];
    const float* u_h1 = (const float*)d_in[5];
    const float* b_h1 = (const float*)d_in[6];
    const float* w_q  = (const float*)d_in[7];
    const float* b_q  = (const float*)d_in[8];

    float* out = (float*)d_out;                       // [B,S,O]
    float* hf  = out + (size_t)Bz * Sz * Hz;          // [B,2,H]

    float *pA0 = nullptr, *pH1 = nullptr;
    cudaGetSymbolAddress((void**)&pA0, g_A0);
    cudaGetSymbolAddress((void**)&pH1, g_H1);

    init_k<<<128, 256>>>();
    gemm256<<<dim3((Bz * Sz) / 64, 4), 256>>>(x, w_h0, b_h0, pA0);
    rnn_k<<<128, 512>>>(u_h0, w_h1, u_h1, b_h1, hf);
    gemm256<<<dim3((Bz * Sz) / 64, 4), 256>>>(pH1, w_q, b_q, out);
}